// round 13
// baseline (speedup 1.0000x reference)
#include <cuda_runtime.h>
#include <math.h>

// Problem constants
#define BB 8192
#define KK 64
#define DD 128
#define HH 64

// Shared memory layout (in floats)
#define XSTR      260                       // duplicated-X row stride (64 slots x 260)
#define OFF_W1    0                         // 128x64 = 8192
#define OFF_X     8192                      // 64*260 = 16640
#define OFF_B1    (OFF_X + 64*XSTR)         // 24832, 64
#define OFF_W2    (OFF_B1 + 64)             // 24896, 128  (layout [h][t], t in {0,1})
#define OFF_B2    (OFF_W2 + 128)            // 25024, 2 (+2 pad)
#define OFF_DEC   (OFF_B2 + 4)              // 25028, 64
#define OFF_KEY   (OFF_DEC + 64)            // 25092, 64
#define OFF_KP    (OFF_KEY + 64)            // 25156, 64
#define SMEM_FLOATS (OFF_KP + 64)           // 25220
#define SMEM_BYTES  (SMEM_FLOATS * 4)       // 100880

// Packed fp32x2 FMA (Blackwell FFMA2): two IEEE fp32 FMAs per instruction,
// bit-identical to scalar fmaf per lane.
__device__ __forceinline__ unsigned long long ffma2(unsigned long long a,
                                                    unsigned long long b,
                                                    unsigned long long c) {
    unsigned long long d;
    asm("fma.rn.f32x2 %0, %1, %2, %3;" : "=l"(d) : "l"(a), "l"(b), "l"(c));
    return d;
}

union F4U {
    float4 f;
    unsigned long long u[2];
    float s[4];
};

union PairU {
    unsigned long long u;
    float f[2];
};

__global__ void __launch_bounds__(256, 2)
gumbel_slot_kernel(const float* __restrict__ slots,
                   const float2* __restrict__ gumbel_u,
                   const float* __restrict__ fix_u,
                   const float* __restrict__ W1,
                   const float* __restrict__ b1,
                   const float* __restrict__ W2,
                   const float* __restrict__ b2,
                   float* __restrict__ out) {
    extern __shared__ float smem[];
    float* sW1  = smem + OFF_W1;
    float* sX   = smem + OFF_X;
    float* sB1  = smem + OFF_B1;
    float* sW2  = smem + OFF_W2;
    float* sB2  = smem + OFF_B2;
    float* sDec = smem + OFF_DEC;
    float* sKey = smem + OFF_KEY;
    float* sKp  = smem + OFF_KP;

    const int tid = threadIdx.x;
    const int b   = blockIdx.x;
    const int tx  = tid & 15;   // h-group: h = 4*tx .. 4*tx+3
    const int ty  = tid >> 4;   // slot-group: s = 4*ty .. 4*ty+3

    // ---- Load W1 (straight copy), b1, W2, b2 ----
    {
        const float4* gW1 = (const float4*)W1;
        float4* s4 = (float4*)sW1;
#pragma unroll
        for (int k = 0; k < 8; k++) s4[tid + 256 * k] = gW1[tid + 256 * k];
    }
    if (tid < 64)  sB1[tid] = b1[tid];
    if (tid < 128) sW2[tid] = W2[tid];
    if (tid < 2)   sB2[tid] = b2[tid];

    // ---- Load this row's X (64 slots x 128), stored DUPLICATED: sX[s][2d]=sX[s][2d+1]=x ----
    {
        const float4* gX = (const float4*)(slots + (size_t)b * (KK * DD));
#pragma unroll
        for (int k = 0; k < 8; k++) {
            int idx = tid + 256 * k;        // float4 index within 64x128 tile
            int s = idx >> 5;               // 32 float4 per slot
            int c = idx & 31;
            float4 v = gX[idx];
            float* row = sX + s * XSTR;
            float4 d0 = make_float4(v.x, v.x, v.y, v.y);
            float4 d1 = make_float4(v.z, v.z, v.w, v.w);
            *(float4*)(row + 8 * c)     = d0;
            *(float4*)(row + 8 * c + 4) = d1;
        }
    }
    __syncthreads();

    // ---- Layer 1 GEMM: acc[slot i][h-pair p], pairs over (h even, h odd) ----
    unsigned long long acc[4][2];
#pragma unroll
    for (int i = 0; i < 4; i++) { acc[i][0] = 0ULL; acc[i][1] = 0ULL; }

    const float* wbase = sW1 + 4 * tx;
    const float* xbase = sX + (4 * ty) * XSTR;

#pragma unroll 4
    for (int d = 0; d < DD; d += 2) {
        F4U wa, wb;
        wa.f = *(const float4*)(wbase + (size_t)d * HH);
        wb.f = *(const float4*)(wbase + (size_t)(d + 1) * HH);
#pragma unroll
        for (int i = 0; i < 4; i++) {
            F4U xv;
            xv.f = *(const float4*)(xbase + i * XSTR + 2 * d); // {x_d,x_d,x_d1,x_d1}
            acc[i][0] = ffma2(xv.u[0], wa.u[0], acc[i][0]);
            acc[i][1] = ffma2(xv.u[0], wa.u[1], acc[i][1]);
            acc[i][0] = ffma2(xv.u[1], wb.u[0], acc[i][0]);
            acc[i][1] = ffma2(xv.u[1], wb.u[1], acc[i][1]);
        }
    }

    // ---- Epilogue: +b1, ReLU, layer 2 partials (4 h each), reduce over 16 lanes ----
    const int h0 = 4 * tx;
    const float bb0 = sB1[h0 + 0], bb1 = sB1[h0 + 1], bb2v = sB1[h0 + 2], bb3 = sB1[h0 + 3];
    const float w20a = sW2[2 * (h0 + 0) + 0], w21a = sW2[2 * (h0 + 0) + 1];
    const float w20b = sW2[2 * (h0 + 1) + 0], w21b = sW2[2 * (h0 + 1) + 1];
    const float w20c = sW2[2 * (h0 + 2) + 0], w21c = sW2[2 * (h0 + 2) + 1];
    const float w20d = sW2[2 * (h0 + 3) + 0], w21d = sW2[2 * (h0 + 3) + 1];

    float pl0[4], pl1[4];
#pragma unroll
    for (int i = 0; i < 4; i++) {
        PairU p0, p1;
        p0.u = acc[i][0];
        p1.u = acc[i][1];
        float hv0 = fmaxf(p0.f[0] + bb0, 0.0f);
        float hv1 = fmaxf(p0.f[1] + bb1, 0.0f);
        float hv2 = fmaxf(p1.f[0] + bb2v, 0.0f);
        float hv3 = fmaxf(p1.f[1] + bb3, 0.0f);
        pl0[i] = hv0 * w20a + hv1 * w20b + hv2 * w20c + hv3 * w20d;
        pl1[i] = hv0 * w21a + hv1 * w21b + hv2 * w21c + hv3 * w21d;
    }

    // butterfly reduce across the 16 tx-lanes (stays inside each 16-lane group)
#pragma unroll
    for (int off = 1; off < 16; off <<= 1) {
#pragma unroll
        for (int i = 0; i < 4; i++) {
            pl0[i] += __shfl_xor_sync(0xFFFFFFFFu, pl0[i], off);
            pl1[i] += __shfl_xor_sync(0xFFFFFFFFu, pl1[i], off);
        }
    }

    if (tx == 0) {
        const float B2_0 = sB2[0], B2_1 = sB2[1];
        const float ULO = 1e-10f;
        const float UHI = (float)(1.0 - 1e-7);
#pragma unroll
        for (int i = 0; i < 4; i++) {
            int s = 4 * ty + i;
            float l0 = pl0[i] + B2_0;
            float l1 = pl1[i] + B2_1;

            // keep_probs = softmax(logits)[1] with max-subtract (matches jax)
            float m  = fmaxf(l0, l1);
            float e0 = expf(l0 - m);
            float e1 = expf(l1 - m);
            float kp = e1 / (e0 + e1);

            // gumbel noise
            float2 gv = gumbel_u[(size_t)b * KK + s];
            float u0 = fminf(fmaxf(gv.x, ULO), UHI);
            float u1 = fminf(fmaxf(gv.y, ULO), UHI);
            float g0 = -logf(-logf(u0));
            float g1 = -logf(-logf(u1));

            // argmax(y_soft) == argmax(logits + g); tie -> index 0 -> decision 0
            float dec = ((l1 + g1) > (l0 + g0)) ? 1.0f : 0.0f;

            sDec[s] = dec;
            sKp[s]  = kp;
            sKey[s] = (dec != 0.0f) ? -INFINITY : fix_u[(size_t)b * KK + s];
        }
    }
    __syncthreads();

    // ---- ensure minimum slots (LOW_BOUND=1): if no active slot, activate argmax(fix_u) ----
    if (tid == 0) {
        bool any = false;
        for (int s = 0; s < KK; s++) {
            if (sDec[s] != 0.0f) { any = true; break; }
        }
        if (!any) {
            float best = sKey[0];
            int bi = 0;
            for (int s = 1; s < KK; s++) {
                float k = sKey[s];
                if (k > best) { best = k; bi = s; }  // strict > : lowest index on ties
            }
            sDec[bi] = 1.0f;
        }
    }
    __syncthreads();

    if (tid < KK) {
        out[(size_t)b * KK + tid] = sDec[tid];
        out[(size_t)BB * KK + (size_t)b * KK + tid] = sKp[tid];
    }
}

extern "C" void kernel_launch(void* const* d_in, const int* in_sizes, int n_in,
                              void* d_out, int out_size) {
    // Map inputs by element count (all distinct); fall back to positional order.
    const float* slots = nullptr;
    const float* gu    = nullptr;
    const float* fixu  = nullptr;
    const float* W1    = nullptr;
    const float* b1    = nullptr;
    const float* W2    = nullptr;
    const float* b2    = nullptr;

    for (int i = 0; i < n_in; i++) {
        switch (in_sizes[i]) {
            case BB * KK * DD: slots = (const float*)d_in[i]; break;  // 67108864
            case BB * KK * 2:  gu    = (const float*)d_in[i]; break;  // 1048576
            case BB * KK:      fixu  = (const float*)d_in[i]; break;  // 524288
            case DD * HH:      W1    = (const float*)d_in[i]; break;  // 8192
            case HH:           b1    = (const float*)d_in[i]; break;  // 64
            case HH * 2:       W2    = (const float*)d_in[i]; break;  // 128
            case 2:            b2    = (const float*)d_in[i]; break;  // 2
            default: break;
        }
    }
    if (!slots || !gu || !fixu || !W1 || !b1 || !W2 || !b2) {
        slots = (const float*)d_in[0];
        gu    = (const float*)d_in[1];
        fixu  = (const float*)d_in[2];
        W1    = (const float*)d_in[3];
        b1    = (const float*)d_in[4];
        W2    = (const float*)d_in[5];
        b2    = (const float*)d_in[6];
    }

    cudaFuncSetAttribute(gumbel_slot_kernel,
                         cudaFuncAttributeMaxDynamicSharedMemorySize, SMEM_BYTES);

    gumbel_slot_kernel<<<BB, 256, SMEM_BYTES>>>(
        slots, (const float2*)gu, fixu, W1, b1, W2, b2, (float*)d_out);
    (void)out_size;
}

// round 14
// speedup vs baseline: 1.0020x; 1.0020x over previous
#include <cuda_runtime.h>
#include <math.h>

// Problem constants
#define BB 8192
#define KK 64
#define DD 128
#define HH 64

// Shared memory layout (in floats)
#define XSTR      260                       // duplicated-X row stride (64 slots x 260)
#define OFF_W1    0                         // 128x64 = 8192
#define OFF_X     8192                      // 64*260 = 16640
#define OFF_B1    (OFF_X + 64*XSTR)         // 24832, 64
#define OFF_W2    (OFF_B1 + 64)             // 24896, 128  (layout [h][t], t in {0,1})
#define OFF_B2    (OFF_W2 + 128)            // 25024, 2 (+2 pad)
#define OFF_DEC   (OFF_B2 + 4)              // 25028, 64
#define OFF_KEY   (OFF_DEC + 64)            // 25092, 64
#define OFF_KP    (OFF_KEY + 64)            // 25156, 64
#define SMEM_FLOATS (OFF_KP + 64)           // 25220
#define SMEM_BYTES  (SMEM_FLOATS * 4)       // 100880

// Packed fp32x2 FMA (Blackwell FFMA2): two IEEE fp32 FMAs per instruction,
// bit-identical to scalar fmaf per lane.
__device__ __forceinline__ unsigned long long ffma2(unsigned long long a,
                                                    unsigned long long b,
                                                    unsigned long long c) {
    unsigned long long d;
    asm("fma.rn.f32x2 %0, %1, %2, %3;" : "=l"(d) : "l"(a), "l"(b), "l"(c));
    return d;
}

union F4U {
    float4 f;
    unsigned long long u[2];
    float s[4];
};

union PairU {
    unsigned long long u;
    float f[2];
};

__global__ void __launch_bounds__(256, 2)
gumbel_slot_kernel(const float* __restrict__ slots,
                   const float2* __restrict__ gumbel_u,
                   const float* __restrict__ fix_u,
                   const float* __restrict__ W1,
                   const float* __restrict__ b1,
                   const float* __restrict__ W2,
                   const float* __restrict__ b2,
                   float* __restrict__ out) {
    extern __shared__ float smem[];
    float* sW1  = smem + OFF_W1;
    float* sX   = smem + OFF_X;
    float* sB1  = smem + OFF_B1;
    float* sW2  = smem + OFF_W2;
    float* sB2  = smem + OFF_B2;
    float* sDec = smem + OFF_DEC;
    float* sKey = smem + OFF_KEY;
    float* sKp  = smem + OFF_KP;

    const int tid = threadIdx.x;
    const int b   = blockIdx.x;
    const int tx  = tid & 15;   // h-group: h = 4*tx .. 4*tx+3
    const int ty  = tid >> 4;   // slot-group: s = 4*ty .. 4*ty+3

    // ---- Load W1 (straight copy), b1, W2, b2 ----
    {
        const float4* gW1 = (const float4*)W1;
        float4* s4 = (float4*)sW1;
#pragma unroll
        for (int k = 0; k < 8; k++) s4[tid + 256 * k] = gW1[tid + 256 * k];
    }
    if (tid < 64)  sB1[tid] = b1[tid];
    if (tid < 128) sW2[tid] = W2[tid];
    if (tid < 2)   sB2[tid] = b2[tid];

    // ---- Load this row's X (64 slots x 128), stored DUPLICATED: sX[s][2d]=sX[s][2d+1]=x ----
    {
        const float4* gX = (const float4*)(slots + (size_t)b * (KK * DD));
#pragma unroll
        for (int k = 0; k < 8; k++) {
            int idx = tid + 256 * k;        // float4 index within 64x128 tile
            int s = idx >> 5;               // 32 float4 per slot
            int c = idx & 31;
            float4 v = gX[idx];
            float* row = sX + s * XSTR;
            float4 d0 = make_float4(v.x, v.x, v.y, v.y);
            float4 d1 = make_float4(v.z, v.z, v.w, v.w);
            *(float4*)(row + 8 * c)     = d0;
            *(float4*)(row + 8 * c + 4) = d1;
        }
    }
    __syncthreads();

    // ---- Layer 1 GEMM: acc[slot i][h-pair p], pairs over (h even, h odd) ----
    unsigned long long acc[4][2];
#pragma unroll
    for (int i = 0; i < 4; i++) { acc[i][0] = 0ULL; acc[i][1] = 0ULL; }

    const float* wbase = sW1 + 4 * tx;
    const float* xbase = sX + (4 * ty) * XSTR;

#pragma unroll 4
    for (int d = 0; d < DD; d += 2) {
        F4U wa, wb;
        wa.f = *(const float4*)(wbase + (size_t)d * HH);
        wb.f = *(const float4*)(wbase + (size_t)(d + 1) * HH);
#pragma unroll
        for (int i = 0; i < 4; i++) {
            F4U xv;
            xv.f = *(const float4*)(xbase + i * XSTR + 2 * d); // {x_d,x_d,x_d1,x_d1}
            acc[i][0] = ffma2(xv.u[0], wa.u[0], acc[i][0]);
            acc[i][1] = ffma2(xv.u[0], wa.u[1], acc[i][1]);
            acc[i][0] = ffma2(xv.u[1], wb.u[0], acc[i][0]);
            acc[i][1] = ffma2(xv.u[1], wb.u[1], acc[i][1]);
        }
    }

    // ---- Epilogue: +b1, ReLU, layer 2 partials (4 h each), reduce over 16 lanes ----
    const int h0 = 4 * tx;
    const float bb0 = sB1[h0 + 0], bb1 = sB1[h0 + 1], bb2v = sB1[h0 + 2], bb3 = sB1[h0 + 3];
    const float w20a = sW2[2 * (h0 + 0) + 0], w21a = sW2[2 * (h0 + 0) + 1];
    const float w20b = sW2[2 * (h0 + 1) + 0], w21b = sW2[2 * (h0 + 1) + 1];
    const float w20c = sW2[2 * (h0 + 2) + 0], w21c = sW2[2 * (h0 + 2) + 1];
    const float w20d = sW2[2 * (h0 + 3) + 0], w21d = sW2[2 * (h0 + 3) + 1];

    float pl0[4], pl1[4];
#pragma unroll
    for (int i = 0; i < 4; i++) {
        PairU p0, p1;
        p0.u = acc[i][0];
        p1.u = acc[i][1];
        float hv0 = fmaxf(p0.f[0] + bb0, 0.0f);
        float hv1 = fmaxf(p0.f[1] + bb1, 0.0f);
        float hv2 = fmaxf(p1.f[0] + bb2v, 0.0f);
        float hv3 = fmaxf(p1.f[1] + bb3, 0.0f);
        pl0[i] = hv0 * w20a + hv1 * w20b + hv2 * w20c + hv3 * w20d;
        pl1[i] = hv0 * w21a + hv1 * w21b + hv2 * w21c + hv3 * w21d;
    }

    // butterfly reduce across the 16 tx-lanes (stays inside each 16-lane group)
#pragma unroll
    for (int off = 1; off < 16; off <<= 1) {
#pragma unroll
        for (int i = 0; i < 4; i++) {
            pl0[i] += __shfl_xor_sync(0xFFFFFFFFu, pl0[i], off);
            pl1[i] += __shfl_xor_sync(0xFFFFFFFFu, pl1[i], off);
        }
    }

    if (tx == 0) {
        const float B2_0 = sB2[0], B2_1 = sB2[1];
        const float ULO = 1e-10f;
        const float UHI = (float)(1.0 - 1e-7);
#pragma unroll
        for (int i = 0; i < 4; i++) {
            int s = 4 * ty + i;
            float l0 = pl0[i] + B2_0;
            float l1 = pl1[i] + B2_1;

            // keep_probs = softmax(logits)[1] with max-subtract (matches jax)
            float m  = fmaxf(l0, l1);
            float e0 = expf(l0 - m);
            float e1 = expf(l1 - m);
            float kp = e1 / (e0 + e1);

            // gumbel noise
            float2 gv = gumbel_u[(size_t)b * KK + s];
            float u0 = fminf(fmaxf(gv.x, ULO), UHI);
            float u1 = fminf(fmaxf(gv.y, ULO), UHI);
            float g0 = -logf(-logf(u0));
            float g1 = -logf(-logf(u1));

            // argmax(y_soft) == argmax(logits + g); tie -> index 0 -> decision 0
            float dec = ((l1 + g1) > (l0 + g0)) ? 1.0f : 0.0f;

            sDec[s] = dec;
            sKp[s]  = kp;
            sKey[s] = (dec != 0.0f) ? -INFINITY : fix_u[(size_t)b * KK + s];
        }
    }
    __syncthreads();

    // ---- ensure minimum slots (LOW_BOUND=1): if no active slot, activate argmax(fix_u) ----
    if (tid == 0) {
        bool any = false;
        for (int s = 0; s < KK; s++) {
            if (sDec[s] != 0.0f) { any = true; break; }
        }
        if (!any) {
            float best = sKey[0];
            int bi = 0;
            for (int s = 1; s < KK; s++) {
                float k = sKey[s];
                if (k > best) { best = k; bi = s; }  // strict > : lowest index on ties
            }
            sDec[bi] = 1.0f;
        }
    }
    __syncthreads();

    if (tid < KK) {
        out[(size_t)b * KK + tid] = sDec[tid];
        out[(size_t)BB * KK + (size_t)b * KK + tid] = sKp[tid];
    }
}

extern "C" void kernel_launch(void* const* d_in, const int* in_sizes, int n_in,
                              void* d_out, int out_size) {
    // Map inputs by element count (all distinct); fall back to positional order.
    const float* slots = nullptr;
    const float* gu    = nullptr;
    const float* fixu  = nullptr;
    const float* W1    = nullptr;
    const float* b1    = nullptr;
    const float* W2    = nullptr;
    const float* b2    = nullptr;

    for (int i = 0; i < n_in; i++) {
        switch (in_sizes[i]) {
            case BB * KK * DD: slots = (const float*)d_in[i]; break;  // 67108864
            case BB * KK * 2:  gu    = (const float*)d_in[i]; break;  // 1048576
            case BB * KK:      fixu  = (const float*)d_in[i]; break;  // 524288
            case DD * HH:      W1    = (const float*)d_in[i]; break;  // 8192
            case HH:           b1    = (const float*)d_in[i]; break;  // 64
            case HH * 2:       W2    = (const float*)d_in[i]; break;  // 128
            case 2:            b2    = (const float*)d_in[i]; break;  // 2
            default: break;
        }
    }
    if (!slots || !gu || !fixu || !W1 || !b1 || !W2 || !b2) {
        slots = (const float*)d_in[0];
        gu    = (const float*)d_in[1];
        fixu  = (const float*)d_in[2];
        W1    = (const float*)d_in[3];
        b1    = (const float*)d_in[4];
        W2    = (const float*)d_in[5];
        b2    = (const float*)d_in[6];
    }

    cudaFuncSetAttribute(gumbel_slot_kernel,
                         cudaFuncAttributeMaxDynamicSharedMemorySize, SMEM_BYTES);

    gumbel_slot_kernel<<<BB, 256, SMEM_BYTES>>>(
        slots, (const float2*)gu, fixu, W1, b1, W2, b2, (float*)d_out);
    (void)out_size;
}

// round 15
// speedup vs baseline: 1.2302x; 1.2279x over previous
#include <cuda_runtime.h>
#include <math.h>

// Problem constants
#define BB 8192
#define KK 64
#define DD 128
#define HH 64

// Shared memory layout (floats). 2 batch rows per block.
#define XSTR      132                       // X row stride (16B aligned: 132*4=528)
#define OFF_W1    0                         // 128 x 64 (seg-permuted) = 8192
#define OFF_X     8192                      // 2 rows x 64 slots x 132 = 16896
#define OFF_B1    (OFF_X + 2*64*XSTR)       // 25088, 64
#define OFF_W2    (OFF_B1 + 64)             // 25152, 128 (layout [h][t])
#define OFF_B2    (OFF_W2 + 128)            // 25280, 2 (+2 pad)
#define OFF_DEC   (OFF_B2 + 4)              // 25284, 2x64
#define OFF_KEY   (OFF_DEC + 128)           // 25412, 2x64
#define OFF_KP    (OFF_KEY + 128)           // 25540, 2x64
#define SMEM_FLOATS (OFF_KP + 128)          // 25668
#define SMEM_BYTES  (SMEM_FLOATS * 4)       // 102672  (x2 blocks = 200.5KB/SM)

// Packed fp32x2 FMA (Blackwell FFMA2): two IEEE fp32 FMAs, bit-identical to
// scalar fmaf per lane.
__device__ __forceinline__ unsigned long long ffma2(unsigned long long a,
                                                    unsigned long long b,
                                                    unsigned long long c) {
    unsigned long long d;
    asm("fma.rn.f32x2 %0, %1, %2, %3;" : "=l"(d) : "l"(a), "l"(b), "l"(c));
    return d;
}

// Build {x, x} pair in an aligned 64-bit register (ALU, not shared memory).
__device__ __forceinline__ unsigned long long dup2(float x) {
    unsigned long long d;
    asm("mov.b64 %0, {%1, %1};" : "=l"(d) : "f"(x));
    return d;
}

union F4U {
    float4 f;
    unsigned long long u[2];
    float s[4];
};

union PairU {
    unsigned long long u;
    float f[2];
};

__global__ void __launch_bounds__(128, 2)
gumbel_slot_kernel(const float* __restrict__ slots,
                   const float2* __restrict__ gumbel_u,
                   const float* __restrict__ fix_u,
                   const float* __restrict__ W1,
                   const float* __restrict__ b1,
                   const float* __restrict__ W2,
                   const float* __restrict__ b2,
                   float* __restrict__ out) {
    extern __shared__ float smem[];
    float* sW1  = smem + OFF_W1;
    float* sX   = smem + OFF_X;
    float* sB1  = smem + OFF_B1;
    float* sW2  = smem + OFF_W2;
    float* sB2  = smem + OFF_B2;
    float* sDec = smem + OFF_DEC;
    float* sKey = smem + OFF_KEY;
    float* sKp  = smem + OFF_KP;

    const int tid = threadIdx.x;
    const int row = tid >> 6;        // 0,1 : which batch row of this block
    const int tir = tid & 63;        // thread-in-row
    const int tx  = tir & 7;         // h-group: h = 8*tx .. 8*tx+7
    const int ty  = tir >> 3;        // slot base: slots = ty + 8*i, i in [0,8)
    const long long b0 = 2LL * blockIdx.x;

    // ---- W1 -> smem with segment permutation (kills 2-way bank conflict).
    // Row d = 16 float4 segments; segment g stored at slot p(g) = (g>>1)|((g&1)<<3).
    {
        const float4* gW1 = (const float4*)W1;
        float4* s4 = (float4*)sW1;
#pragma unroll
        for (int k = 0; k < 16; k++) {
            int idx = tid + 128 * k;          // 0..2047
            int d = idx >> 4;
            int g = idx & 15;
            int p = (g >> 1) | ((g & 1) << 3);
            s4[d * 16 + p] = gW1[idx];
        }
    }
    if (tid < 64) sB1[tid] = b1[tid];
    sW2[tid] = W2[tid];                       // 128 threads cover 128 values
    if (tid < 2) sB2[tid] = b2[tid];

    // ---- X (2 rows x 64 slots x 128) -> smem plain [s][d], stride XSTR ----
    {
        const float4* gX = (const float4*)(slots + b0 * (KK * DD));
#pragma unroll
        for (int k = 0; k < 32; k++) {
            int idx = tid + 128 * k;          // float4 index, 0..4095
            int r = idx >> 11;                // 2048 float4 per row
            int s = (idx >> 5) & 63;
            int c = idx & 31;
            *(float4*)(sX + r * (64 * XSTR) + s * XSTR + 4 * c) = gX[idx];
        }
    }
    __syncthreads();

    // ---- Layer-1 GEMM: acc[slot i][h-pair p], h-pairs natural from W float4 ----
    unsigned long long acc[8][4];
#pragma unroll
    for (int i = 0; i < 8; i++)
#pragma unroll
        for (int p = 0; p < 4; p++) acc[i][p] = 0ULL;

    const float*  xb = sX + row * (64 * XSTR) + ty * XSTR;  // + i*8*XSTR per slot
    const float4* wb = (const float4*)sW1;

    for (int d0 = 0; d0 < DD; d0 += 4) {
        // W: h = 8tx..8tx+3 at permuted slot tx; h = 8tx+4..8tx+7 at slot 8+tx
        F4U w0[4], w1[4];
#pragma unroll
        for (int j = 0; j < 4; j++) {
            w0[j].f = wb[(d0 + j) * 16 + tx];
            w1[j].f = wb[(d0 + j) * 16 + 8 + tx];
        }
#pragma unroll
        for (int i = 0; i < 8; i++) {
            F4U xv;
            xv.f = *(const float4*)(xb + i * (8 * XSTR) + d0);  // x[d0..d0+3]
#pragma unroll
            for (int j = 0; j < 4; j++) {
                unsigned long long xd = dup2(xv.s[j]);
                acc[i][0] = ffma2(xd, w0[j].u[0], acc[i][0]);
                acc[i][1] = ffma2(xd, w0[j].u[1], acc[i][1]);
                acc[i][2] = ffma2(xd, w1[j].u[0], acc[i][2]);
                acc[i][3] = ffma2(xd, w1[j].u[1], acc[i][3]);
            }
        }
    }

    // ---- Epilogue: +b1, ReLU, layer-2 partials, reduce over 8 tx-lanes ----
    const int h0 = 8 * tx;
    float bb[8], w2a[8], w2b[8];
#pragma unroll
    for (int e = 0; e < 8; e++) {
        bb[e]  = sB1[h0 + e];
        w2a[e] = sW2[2 * (h0 + e) + 0];
        w2b[e] = sW2[2 * (h0 + e) + 1];
    }

    float pl0[8], pl1[8];
#pragma unroll
    for (int i = 0; i < 8; i++) {
        float a0 = 0.0f, a1 = 0.0f;
#pragma unroll
        for (int p = 0; p < 4; p++) {
            PairU pu;
            pu.u = acc[i][p];
            float hv0 = fmaxf(pu.f[0] + bb[2 * p + 0], 0.0f);
            float hv1 = fmaxf(pu.f[1] + bb[2 * p + 1], 0.0f);
            a0 += hv0 * w2a[2 * p + 0] + hv1 * w2a[2 * p + 1];
            a1 += hv0 * w2b[2 * p + 0] + hv1 * w2b[2 * p + 1];
        }
        pl0[i] = a0;
        pl1[i] = a1;
    }

    // butterfly reduce across the 8 tx-lanes (stays inside 8-lane groups)
#pragma unroll
    for (int off = 1; off < 8; off <<= 1) {
#pragma unroll
        for (int i = 0; i < 8; i++) {
            pl0[i] += __shfl_xor_sync(0xFFFFFFFFu, pl0[i], off);
            pl1[i] += __shfl_xor_sync(0xFFFFFFFFu, pl1[i], off);
        }
    }

    if (tx == 0) {
        const long long b = b0 + row;
        const float B2_0 = sB2[0], B2_1 = sB2[1];
        const float ULO = 1e-10f;
        const float UHI = (float)(1.0 - 1e-7);
        float* rDec = sDec + row * 64;
        float* rKey = sKey + row * 64;
        float* rKp  = sKp  + row * 64;
#pragma unroll
        for (int i = 0; i < 8; i++) {
            int s = ty + 8 * i;
            float l0 = pl0[i] + B2_0;
            float l1 = pl1[i] + B2_1;

            // keep_probs = softmax(logits)[1] with max-subtract (matches jax)
            float m  = fmaxf(l0, l1);
            float e0 = expf(l0 - m);
            float e1 = expf(l1 - m);
            float kp = e1 / (e0 + e1);

            // gumbel noise
            float2 gv = gumbel_u[b * KK + s];
            float u0 = fminf(fmaxf(gv.x, ULO), UHI);
            float u1 = fminf(fmaxf(gv.y, ULO), UHI);
            float g0 = -logf(-logf(u0));
            float g1 = -logf(-logf(u1));

            // argmax(y_soft) == argmax(logits + g); tie -> index 0 -> decision 0
            float dec = ((l1 + g1) > (l0 + g0)) ? 1.0f : 0.0f;

            rDec[s] = dec;
            rKp[s]  = kp;
            rKey[s] = (dec != 0.0f) ? -INFINITY : fix_u[b * KK + s];
        }
    }
    __syncthreads();

    // ---- ensure minimum slots (LOW_BOUND=1) per row ----
    if (tir == 0) {
        float* rDec = sDec + row * 64;
        float* rKey = sKey + row * 64;
        bool any = false;
        for (int s = 0; s < KK; s++) {
            if (rDec[s] != 0.0f) { any = true; break; }
        }
        if (!any) {
            float best = rKey[0];
            int bi = 0;
            for (int s = 1; s < KK; s++) {
                float k = rKey[s];
                if (k > best) { best = k; bi = s; }  // strict > : lowest index wins ties
            }
            rDec[bi] = 1.0f;
        }
    }
    __syncthreads();

    // ---- output: decision then keep_probs ----
    {
        const long long b = b0 + row;
        out[b * KK + tir] = sDec[row * 64 + tir];
        out[(long long)BB * KK + b * KK + tir] = sKp[row * 64 + tir];
    }
}

extern "C" void kernel_launch(void* const* d_in, const int* in_sizes, int n_in,
                              void* d_out, int out_size) {
    // Map inputs by element count (all distinct); fall back to positional order.
    const float* slots = nullptr;
    const float* gu    = nullptr;
    const float* fixu  = nullptr;
    const float* W1    = nullptr;
    const float* b1    = nullptr;
    const float* W2    = nullptr;
    const float* b2    = nullptr;

    for (int i = 0; i < n_in; i++) {
        switch (in_sizes[i]) {
            case BB * KK * DD: slots = (const float*)d_in[i]; break;  // 67108864
            case BB * KK * 2:  gu    = (const float*)d_in[i]; break;  // 1048576
            case BB * KK:      fixu  = (const float*)d_in[i]; break;  // 524288
            case DD * HH:      W1    = (const float*)d_in[i]; break;  // 8192
            case HH:           b1    = (const float*)d_in[i]; break;  // 64
            case HH * 2:       W2    = (const float*)d_in[i]; break;  // 128
            case 2:            b2    = (const float*)d_in[i]; break;  // 2
            default: break;
        }
    }
    if (!slots || !gu || !fixu || !W1 || !b1 || !W2 || !b2) {
        slots = (const float*)d_in[0];
        gu    = (const float*)d_in[1];
        fixu  = (const float*)d_in[2];
        W1    = (const float*)d_in[3];
        b1    = (const float*)d_in[4];
        W2    = (const float*)d_in[5];
        b2    = (const float*)d_in[6];
    }

    cudaFuncSetAttribute(gumbel_slot_kernel,
                         cudaFuncAttributeMaxDynamicSharedMemorySize, SMEM_BYTES);

    gumbel_slot_kernel<<<BB / 2, 128, SMEM_BYTES>>>(
        slots, (const float2*)gu, fixu, W1, b1, W2, b2, (float*)d_out);
    (void)out_size;
}

// round 16
// speedup vs baseline: 1.4060x; 1.1429x over previous
#include <cuda_runtime.h>
#include <math.h>

// Problem constants
#define BB 8192
#define KK 64
#define DD 128
#define HH 64

// Shared memory layout (floats). 2 batch rows per block.
#define XSTR      132                       // X row stride (16B aligned, bank-clean)
#define OFF_W1    0                         // 128 x 64 (seg-permuted) = 8192
#define OFF_X     8192                      // 2 rows x 64 slots x 132 = 16896
#define OFF_B1    (OFF_X + 2*64*XSTR)       // 25088, 64
#define OFF_W2    (OFF_B1 + 64)             // 25152, 128 (layout [h][t])
#define OFF_B2    (OFF_W2 + 128)            // 25280, 2 (+2 pad)
#define OFF_DEC   (OFF_B2 + 4)              // 25284, 2x64
#define OFF_KEY   (OFF_DEC + 128)           // 25412, 2x64
#define OFF_KP    (OFF_KEY + 128)           // 25540, 2x64
#define SMEM_FLOATS (OFF_KP + 128)          // 25668
#define SMEM_BYTES  (SMEM_FLOATS * 4)       // 102672  (x2 blocks = 200.5KB/SM)

// Packed fp32x2 FMA (Blackwell FFMA2): two IEEE fp32 FMAs, bit-identical to
// scalar fmaf per lane.
__device__ __forceinline__ unsigned long long ffma2(unsigned long long a,
                                                    unsigned long long b,
                                                    unsigned long long c) {
    unsigned long long d;
    asm("fma.rn.f32x2 %0, %1, %2, %3;" : "=l"(d) : "l"(a), "l"(b), "l"(c));
    return d;
}

// Build {x, x} pair in a 64-bit register (ALU, not shared memory).
__device__ __forceinline__ unsigned long long dup2(float x) {
    unsigned long long d;
    asm("mov.b64 %0, {%1, %1};" : "=l"(d) : "f"(x));
    return d;
}

union F4U {
    float4 f;
    unsigned long long u[2];
    float s[4];
};

union PairU {
    unsigned long long u;
    float f[2];
};

__global__ void __launch_bounds__(256, 2)
gumbel_slot_kernel(const float* __restrict__ slots,
                   const float2* __restrict__ gumbel_u,
                   const float* __restrict__ fix_u,
                   const float* __restrict__ W1,
                   const float* __restrict__ b1,
                   const float* __restrict__ W2,
                   const float* __restrict__ b2,
                   float* __restrict__ out) {
    extern __shared__ float smem[];
    float* sW1  = smem + OFF_W1;
    float* sX   = smem + OFF_X;
    float* sB1  = smem + OFF_B1;
    float* sW2  = smem + OFF_W2;
    float* sB2  = smem + OFF_B2;
    float* sDec = smem + OFF_DEC;
    float* sKey = smem + OFF_KEY;
    float* sKp  = smem + OFF_KP;

    const int tid = threadIdx.x;
    const int row = tid >> 7;        // 0,1 : which batch row of this block
    const int tir = tid & 127;       // thread-in-row
    const int tx  = tir & 7;         // h-group: h = 8*tx .. 8*tx+7
    const int ty  = tir >> 3;        // slot base: slots = ty + 16*i, i in [0,4)
    const long long b0 = 2LL * blockIdx.x;

    // ---- W1 -> smem with segment permutation (conflict-free GEMM reads).
    // Row d = 16 float4 segments; segment g stored at slot p(g) = (g>>1)|((g&1)<<3).
    {
        const float4* gW1 = (const float4*)W1;
        float4* s4 = (float4*)sW1;
#pragma unroll
        for (int k = 0; k < 8; k++) {
            int idx = tid + 256 * k;          // 0..2047
            int d = idx >> 4;
            int g = idx & 15;
            int p = (g >> 1) | ((g & 1) << 3);
            s4[d * 16 + p] = gW1[idx];
        }
    }
    if (tid < 64)  sB1[tid] = b1[tid];
    if (tid < 128) sW2[tid] = W2[tid];
    if (tid < 2)   sB2[tid] = b2[tid];

    // ---- X (2 rows x 64 slots x 128) -> smem plain [s][d], stride XSTR ----
    {
        const float4* gX = (const float4*)(slots + b0 * (KK * DD));
#pragma unroll
        for (int k = 0; k < 16; k++) {
            int idx = tid + 256 * k;          // float4 index, 0..4095
            int r = idx >> 11;                // 2048 float4 per row
            int s = (idx >> 5) & 63;
            int c = idx & 31;
            *(float4*)(sX + r * (64 * XSTR) + s * XSTR + 4 * c) = gX[idx];
        }
    }
    __syncthreads();

    // ---- Layer-1 GEMM: acc[slot i][h-pair p], h-pairs natural from W float4 ----
    unsigned long long acc[4][4];
#pragma unroll
    for (int i = 0; i < 4; i++)
#pragma unroll
        for (int p = 0; p < 4; p++) acc[i][p] = 0ULL;

    const float*  xb = sX + row * (64 * XSTR) + ty * XSTR;  // + i*16*XSTR per slot
    const float4* wb = (const float4*)sW1;

    for (int d0 = 0; d0 < DD; d0 += 4) {
        // W: h = 8tx..8tx+3 at permuted slot tx; h = 8tx+4..8tx+7 at slot 8+tx
        F4U w0[4], w1[4];
#pragma unroll
        for (int j = 0; j < 4; j++) {
            w0[j].f = wb[(d0 + j) * 16 + tx];
            w1[j].f = wb[(d0 + j) * 16 + 8 + tx];
        }
        // Batch the 4 X loads (MLP) before the FFMA2 burst.
        F4U xv[4];
#pragma unroll
        for (int i = 0; i < 4; i++)
            xv[i].f = *(const float4*)(xb + i * (16 * XSTR) + d0);  // x[d0..d0+3]
#pragma unroll
        for (int i = 0; i < 4; i++) {
#pragma unroll
            for (int j = 0; j < 4; j++) {
                unsigned long long xd = dup2(xv[i].s[j]);
                acc[i][0] = ffma2(xd, w0[j].u[0], acc[i][0]);
                acc[i][1] = ffma2(xd, w0[j].u[1], acc[i][1]);
                acc[i][2] = ffma2(xd, w1[j].u[0], acc[i][2]);
                acc[i][3] = ffma2(xd, w1[j].u[1], acc[i][3]);
            }
        }
    }

    // ---- Epilogue: +b1, ReLU, layer-2 partials, reduce over 8 tx-lanes ----
    const int h0 = 8 * tx;
    float bb[8], w2a[8], w2b[8];
#pragma unroll
    for (int e = 0; e < 8; e++) {
        bb[e]  = sB1[h0 + e];
        w2a[e] = sW2[2 * (h0 + e) + 0];
        w2b[e] = sW2[2 * (h0 + e) + 1];
    }

    float pl0[4], pl1[4];
#pragma unroll
    for (int i = 0; i < 4; i++) {
        float a0 = 0.0f, a1 = 0.0f;
#pragma unroll
        for (int p = 0; p < 4; p++) {
            PairU pu;
            pu.u = acc[i][p];
            float hv0 = fmaxf(pu.f[0] + bb[2 * p + 0], 0.0f);
            float hv1 = fmaxf(pu.f[1] + bb[2 * p + 1], 0.0f);
            a0 += hv0 * w2a[2 * p + 0] + hv1 * w2a[2 * p + 1];
            a1 += hv0 * w2b[2 * p + 0] + hv1 * w2b[2 * p + 1];
        }
        pl0[i] = a0;
        pl1[i] = a1;
    }

    // butterfly reduce across the 8 tx-lanes (stays inside 8-lane groups)
#pragma unroll
    for (int off = 1; off < 8; off <<= 1) {
#pragma unroll
        for (int i = 0; i < 4; i++) {
            pl0[i] += __shfl_xor_sync(0xFFFFFFFFu, pl0[i], off);
            pl1[i] += __shfl_xor_sync(0xFFFFFFFFu, pl1[i], off);
        }
    }

    if (tx == 0) {
        const long long b = b0 + row;
        const float B2_0 = sB2[0], B2_1 = sB2[1];
        const float ULO = 1e-10f;
        const float UHI = (float)(1.0 - 1e-7);
        float* rDec = sDec + row * 64;
        float* rKey = sKey + row * 64;
        float* rKp  = sKp  + row * 64;
#pragma unroll
        for (int i = 0; i < 4; i++) {
            int s = ty + 16 * i;
            float l0 = pl0[i] + B2_0;
            float l1 = pl1[i] + B2_1;

            // keep_probs = softmax(logits)[1] with max-subtract (matches jax)
            float m  = fmaxf(l0, l1);
            float e0 = expf(l0 - m);
            float e1 = expf(l1 - m);
            float kp = e1 / (e0 + e1);

            // gumbel noise
            float2 gv = gumbel_u[b * KK + s];
            float u0 = fminf(fmaxf(gv.x, ULO), UHI);
            float u1 = fminf(fmaxf(gv.y, ULO), UHI);
            float g0 = -logf(-logf(u0));
            float g1 = -logf(-logf(u1));

            // argmax(y_soft) == argmax(logits + g); tie -> index 0 -> decision 0
            float dec = ((l1 + g1) > (l0 + g0)) ? 1.0f : 0.0f;

            rDec[s] = dec;
            rKp[s]  = kp;
            rKey[s] = (dec != 0.0f) ? -INFINITY : fix_u[b * KK + s];
        }
    }
    __syncthreads();

    // ---- ensure minimum slots (LOW_BOUND=1) per row ----
    if (tir == 0) {
        float* rDec = sDec + row * 64;
        float* rKey = sKey + row * 64;
        bool any = false;
        for (int s = 0; s < KK; s++) {
            if (rDec[s] != 0.0f) { any = true; break; }
        }
        if (!any) {
            float best = rKey[0];
            int bi = 0;
            for (int s = 1; s < KK; s++) {
                float k = rKey[s];
                if (k > best) { best = k; bi = s; }  // strict > : lowest index wins ties
            }
            rDec[bi] = 1.0f;
        }
    }
    __syncthreads();

    // ---- output: decision then keep_probs ----
    if (tir < 64) {
        const long long b = b0 + row;
        out[b * KK + tir] = sDec[row * 64 + tir];
        out[(long long)BB * KK + b * KK + tir] = sKp[row * 64 + tir];
    }
}

extern "C" void kernel_launch(void* const* d_in, const int* in_sizes, int n_in,
                              void* d_out, int out_size) {
    // Map inputs by element count (all distinct); fall back to positional order.
    const float* slots = nullptr;
    const float* gu    = nullptr;
    const float* fixu  = nullptr;
    const float* W1    = nullptr;
    const float* b1    = nullptr;
    const float* W2    = nullptr;
    const float* b2    = nullptr;

    for (int i = 0; i < n_in; i++) {
        switch (in_sizes[i]) {
            case BB * KK * DD: slots = (const float*)d_in[i]; break;  // 67108864
            case BB * KK * 2:  gu    = (const float*)d_in[i]; break;  // 1048576
            case BB * KK:      fixu  = (const float*)d_in[i]; break;  // 524288
            case DD * HH:      W1    = (const float*)d_in[i]; break;  // 8192
            case HH:           b1    = (const float*)d_in[i]; break;  // 64
            case HH * 2:       W2    = (const float*)d_in[i]; break;  // 128
            case 2:            b2    = (const float*)d_in[i]; break;  // 2
            default: break;
        }
    }
    if (!slots || !gu || !fixu || !W1 || !b1 || !W2 || !b2) {
        slots = (const float*)d_in[0];
        gu    = (const float*)d_in[1];
        fixu  = (const float*)d_in[2];
        W1    = (const float*)d_in[3];
        b1    = (const float*)d_in[4];
        W2    = (const float*)d_in[5];
        b2    = (const float*)d_in[6];
    }

    cudaFuncSetAttribute(gumbel_slot_kernel,
                         cudaFuncAttributeMaxDynamicSharedMemorySize, SMEM_BYTES);

    gumbel_slot_kernel<<<BB / 2, 256, SMEM_BYTES>>>(
        slots, (const float2*)gu, fixu, W1, b1, W2, b2, (float*)d_out);
    (void)out_size;
}

// round 17
// speedup vs baseline: 1.4091x; 1.0022x over previous
#include <cuda_runtime.h>
#include <math.h>

// Problem constants
#define BB 8192
#define KK 64
#define DD 128
#define HH 64

// Shared memory layout (floats). 2 batch rows per block.
#define XSTR      132                       // X row stride (16B aligned, bank-clean)
#define OFF_W1    0                         // 128 x 64 (seg-permuted) = 8192
#define OFF_X     8192                      // 2 rows x 64 slots x 132 = 16896
#define OFF_B1    (OFF_X + 2*64*XSTR)       // 25088, 64
#define OFF_W2    (OFF_B1 + 64)             // 25152, 128 (layout [h][t])
#define OFF_B2    (OFF_W2 + 128)            // 25280, 2 (+2 pad)
#define OFF_DEC   (OFF_B2 + 4)              // 25284, 2x64
#define OFF_KEY   (OFF_DEC + 128)           // 25412, 2x64
#define OFF_KP    (OFF_KEY + 128)           // 25540, 2x64
#define SMEM_FLOATS (OFF_KP + 128)          // 25668
#define SMEM_BYTES  (SMEM_FLOATS * 4)       // 102672  (x2 blocks = 200.5KB/SM)

// Packed fp32x2 FMA (Blackwell FFMA2): two IEEE fp32 FMAs, bit-identical to
// scalar fmaf per lane.
__device__ __forceinline__ unsigned long long ffma2(unsigned long long a,
                                                    unsigned long long b,
                                                    unsigned long long c) {
    unsigned long long d;
    asm("fma.rn.f32x2 %0, %1, %2, %3;" : "=l"(d) : "l"(a), "l"(b), "l"(c));
    return d;
}

// Build {x, x} pair in a 64-bit register (ALU, not shared memory).
__device__ __forceinline__ unsigned long long dup2(float x) {
    unsigned long long d;
    asm("mov.b64 %0, {%1, %1};" : "=l"(d) : "f"(x));
    return d;
}

union F4U {
    float4 f;
    unsigned long long u[2];
    float s[4];
};

union PairU {
    unsigned long long u;
    float f[2];
};

__global__ void __launch_bounds__(256, 2)
gumbel_slot_kernel(const float* __restrict__ slots,
                   const float2* __restrict__ gumbel_u,
                   const float* __restrict__ fix_u,
                   const float* __restrict__ W1,
                   const float* __restrict__ b1,
                   const float* __restrict__ W2,
                   const float* __restrict__ b2,
                   float* __restrict__ out) {
    extern __shared__ float smem[];
    float* sW1  = smem + OFF_W1;
    float* sX   = smem + OFF_X;
    float* sB1  = smem + OFF_B1;
    float* sW2  = smem + OFF_W2;
    float* sB2  = smem + OFF_B2;
    float* sDec = smem + OFF_DEC;
    float* sKey = smem + OFF_KEY;
    float* sKp  = smem + OFF_KP;

    const int tid = threadIdx.x;
    const int row = tid >> 7;        // 0,1 : which batch row of this block
    const int tir = tid & 127;       // thread-in-row
    const int tx  = tir & 7;         // h-group: h = 8*tx .. 8*tx+7
    const int ty  = tir >> 3;        // slot base: slots = ty + 16*i, i in [0,4)
    const long long b0 = 2LL * blockIdx.x;

    // ---- W1 -> smem with segment permutation (conflict-free GEMM reads).
    // Row d = 16 float4 segments; segment g stored at slot p(g) = (g>>1)|((g&1)<<3).
    {
        const float4* gW1 = (const float4*)W1;
        float4* s4 = (float4*)sW1;
#pragma unroll
        for (int k = 0; k < 8; k++) {
            int idx = tid + 256 * k;          // 0..2047
            int d = idx >> 4;
            int g = idx & 15;
            int p = (g >> 1) | ((g & 1) << 3);
            s4[d * 16 + p] = gW1[idx];
        }
    }
    if (tid < 64)  sB1[tid] = b1[tid];
    if (tid < 128) sW2[tid] = W2[tid];
    if (tid < 2)   sB2[tid] = b2[tid];

    // ---- X (2 rows x 64 slots x 128) -> smem plain [s][d], stride XSTR ----
    {
        const float4* gX = (const float4*)(slots + b0 * (KK * DD));
#pragma unroll
        for (int k = 0; k < 16; k++) {
            int idx = tid + 256 * k;          // float4 index, 0..4095
            int r = idx >> 11;                // 2048 float4 per row
            int s = (idx >> 5) & 63;
            int c = idx & 31;
            *(float4*)(sX + r * (64 * XSTR) + s * XSTR + 4 * c) = gX[idx];
        }
    }
    __syncthreads();

    // ---- Layer-1 GEMM: acc[slot i][h-pair p], h-pairs natural from W float4 ----
    unsigned long long acc[4][4];
#pragma unroll
    for (int i = 0; i < 4; i++)
#pragma unroll
        for (int p = 0; p < 4; p++) acc[i][p] = 0ULL;

    const float*  xb = sX + row * (64 * XSTR) + ty * XSTR;  // + i*16*XSTR per slot
    const float4* wb = (const float4*)sW1;

    for (int d0 = 0; d0 < DD; d0 += 4) {
        // W: h = 8tx..8tx+3 at permuted slot tx; h = 8tx+4..8tx+7 at slot 8+tx
        F4U w0[4], w1[4];
#pragma unroll
        for (int j = 0; j < 4; j++) {
            w0[j].f = wb[(d0 + j) * 16 + tx];
            w1[j].f = wb[(d0 + j) * 16 + 8 + tx];
        }
        // Batch the 4 X loads (MLP) before the FFMA2 burst.
        F4U xv[4];
#pragma unroll
        for (int i = 0; i < 4; i++)
            xv[i].f = *(const float4*)(xb + i * (16 * XSTR) + d0);  // x[d0..d0+3]
#pragma unroll
        for (int i = 0; i < 4; i++) {
#pragma unroll
            for (int j = 0; j < 4; j++) {
                unsigned long long xd = dup2(xv[i].s[j]);
                acc[i][0] = ffma2(xd, w0[j].u[0], acc[i][0]);
                acc[i][1] = ffma2(xd, w0[j].u[1], acc[i][1]);
                acc[i][2] = ffma2(xd, w1[j].u[0], acc[i][2]);
                acc[i][3] = ffma2(xd, w1[j].u[1], acc[i][3]);
            }
        }
    }

    // ---- Epilogue: +b1, ReLU, layer-2 partials, reduce over 8 tx-lanes ----
    const int h0 = 8 * tx;
    float bb[8], w2a[8], w2b[8];
#pragma unroll
    for (int e = 0; e < 8; e++) {
        bb[e]  = sB1[h0 + e];
        w2a[e] = sW2[2 * (h0 + e) + 0];
        w2b[e] = sW2[2 * (h0 + e) + 1];
    }

    float pl0[4], pl1[4];
#pragma unroll
    for (int i = 0; i < 4; i++) {
        float a0 = 0.0f, a1 = 0.0f;
#pragma unroll
        for (int p = 0; p < 4; p++) {
            PairU pu;
            pu.u = acc[i][p];
            float hv0 = fmaxf(pu.f[0] + bb[2 * p + 0], 0.0f);
            float hv1 = fmaxf(pu.f[1] + bb[2 * p + 1], 0.0f);
            a0 += hv0 * w2a[2 * p + 0] + hv1 * w2a[2 * p + 1];
            a1 += hv0 * w2b[2 * p + 0] + hv1 * w2b[2 * p + 1];
        }
        pl0[i] = a0;
        pl1[i] = a1;
    }

    // butterfly reduce across the 8 tx-lanes (stays inside 8-lane groups)
#pragma unroll
    for (int off = 1; off < 8; off <<= 1) {
#pragma unroll
        for (int i = 0; i < 4; i++) {
            pl0[i] += __shfl_xor_sync(0xFFFFFFFFu, pl0[i], off);
            pl1[i] += __shfl_xor_sync(0xFFFFFFFFu, pl1[i], off);
        }
    }

    if (tx == 0) {
        const long long b = b0 + row;
        const float B2_0 = sB2[0], B2_1 = sB2[1];
        const float ULO = 1e-10f;
        const float UHI = (float)(1.0 - 1e-7);
        float* rDec = sDec + row * 64;
        float* rKey = sKey + row * 64;
        float* rKp  = sKp  + row * 64;
#pragma unroll
        for (int i = 0; i < 4; i++) {
            int s = ty + 16 * i;
            float l0 = pl0[i] + B2_0;
            float l1 = pl1[i] + B2_1;

            // keep_probs = softmax(logits)[1] with max-subtract (matches jax)
            float m  = fmaxf(l0, l1);
            float e0 = expf(l0 - m);
            float e1 = expf(l1 - m);
            float kp = e1 / (e0 + e1);

            // gumbel noise
            float2 gv = gumbel_u[b * KK + s];
            float u0 = fminf(fmaxf(gv.x, ULO), UHI);
            float u1 = fminf(fmaxf(gv.y, ULO), UHI);
            float g0 = -logf(-logf(u0));
            float g1 = -logf(-logf(u1));

            // argmax(y_soft) == argmax(logits + g); tie -> index 0 -> decision 0
            float dec = ((l1 + g1) > (l0 + g0)) ? 1.0f : 0.0f;

            rDec[s] = dec;
            rKp[s]  = kp;
            rKey[s] = (dec != 0.0f) ? -INFINITY : fix_u[b * KK + s];
        }
    }
    __syncthreads();

    // ---- ensure minimum slots (LOW_BOUND=1) per row ----
    if (tir == 0) {
        float* rDec = sDec + row * 64;
        float* rKey = sKey + row * 64;
        bool any = false;
        for (int s = 0; s < KK; s++) {
            if (rDec[s] != 0.0f) { any = true; break; }
        }
        if (!any) {
            float best = rKey[0];
            int bi = 0;
            for (int s = 1; s < KK; s++) {
                float k = rKey[s];
                if (k > best) { best = k; bi = s; }  // strict > : lowest index wins ties
            }
            rDec[bi] = 1.0f;
        }
    }
    __syncthreads();

    // ---- output: decision then keep_probs ----
    if (tir < 64) {
        const long long b = b0 + row;
        out[b * KK + tir] = sDec[row * 64 + tir];
        out[(long long)BB * KK + b * KK + tir] = sKp[row * 64 + tir];
    }
}

extern "C" void kernel_launch(void* const* d_in, const int* in_sizes, int n_in,
                              void* d_out, int out_size) {
    // Map inputs by element count (all distinct); fall back to positional order.
    const float* slots = nullptr;
    const float* gu    = nullptr;
    const float* fixu  = nullptr;
    const float* W1    = nullptr;
    const float* b1    = nullptr;
    const float* W2    = nullptr;
    const float* b2    = nullptr;

    for (int i = 0; i < n_in; i++) {
        switch (in_sizes[i]) {
            case BB * KK * DD: slots = (const float*)d_in[i]; break;  // 67108864
            case BB * KK * 2:  gu    = (const float*)d_in[i]; break;  // 1048576
            case BB * KK:      fixu  = (const float*)d_in[i]; break;  // 524288
            case DD * HH:      W1    = (const float*)d_in[i]; break;  // 8192
            case HH:           b1    = (const float*)d_in[i]; break;  // 64
            case HH * 2:       W2    = (const float*)d_in[i]; break;  // 128
            case 2:            b2    = (const float*)d_in[i]; break;  // 2
            default: break;
        }
    }
    if (!slots || !gu || !fixu || !W1 || !b1 || !W2 || !b2) {
        slots = (const float*)d_in[0];
        gu    = (const float*)d_in[1];
        fixu  = (const float*)d_in[2];
        W1    = (const float*)d_in[3];
        b1    = (const float*)d_in[4];
        W2    = (const float*)d_in[5];
        b2    = (const float*)d_in[6];
    }

    cudaFuncSetAttribute(gumbel_slot_kernel,
                         cudaFuncAttributeMaxDynamicSharedMemorySize, SMEM_BYTES);

    gumbel_slot_kernel<<<BB / 2, 256, SMEM_BYTES>>>(
        slots, (const float2*)gu, fixu, W1, b1, W2, b2, (float*)d_out);
    (void)out_size;
}